// round 12
// baseline (speedup 1.0000x reference)
#include <cuda_runtime.h>
#include <cuda_bf16.h>
#include <cstdint>

// Problem constants
#define BATCH 2
#define LSEQ  2048
#define HID   2048
#define NH    16
#define NKV   8
#define HD    128
#define NIMG  1024
#define MROWS (BATCH*LSEQ)   // 4096

typedef unsigned long long u64;

// ---------------- scratch (device globals; no allocation allowed) ----------
__device__ float g_q [(size_t)BATCH*LSEQ*NH *HD];
__device__ float g_k [(size_t)BATCH*LSEQ*NKV*HD];
__device__ float g_v [(size_t)BATCH*LSEQ*NKV*HD];
__device__ float g_ao[(size_t)BATCH*LSEQ*NH *HD];

// ---------------- f32x2 helpers (Blackwell packed fp32, baseline PTX) ------
__device__ __forceinline__ void ffma2(u64& d, u64 a, u64 b) {
    asm("fma.rn.f32x2 %0, %1, %2, %0;" : "+l"(d) : "l"(a), "l"(b));
}
__device__ __forceinline__ u64 pack2(float x, float y) {
    u64 r; asm("mov.b64 %0, {%1, %2};" : "=l"(r) : "f"(x), "f"(y)); return r;
}
__device__ __forceinline__ void unpack2(u64 d, float& x, float& y) {
    asm("mov.b64 {%0, %1}, %2;" : "=f"(x), "=f"(y) : "l"(d));
}

// ---------------- GEMM core: 128x64 tile, BK=16, 256 thr, 4m x 8n ----------
// C[m,n] = sum_k A[m,k]*B[n,k].
// As[kk][m] natural (132 pad). Read: 1 LDS.128 (32 distinct addrs = 4 wf,
//   the floor). Bs skewed: 8-float segment s at 8s+4(s>>2) -> the 8 thread
//   segments hit 8 distinct quads = conflict-free (1 wf per LDS.128).
// acc = n-pairs (u64): 16 FFMA2/kk, 8 splat MOVs, 3 LDS -> all pipes under
//   the fma bound. ~80 regs -> 3 CTAs/SM (6 warps/SMSP).
#define APAD 132
#define BPAD 72
__device__ __forceinline__ int bs_off(int n) { return n + ((n >> 5) << 2); }

__device__ __forceinline__ void gemm_core(
        const float* __restrict__ Ab, const float* __restrict__ Bb,
        float* __restrict__ C, int N, int K, int mb, int nb,
        float (*As)[16][APAD], float (*Bs)[16][BPAD])
{
    const int tid = threadIdx.x;
    const int ty  = tid >> 3;          // 0..31 -> m = ty*4 + i
    const int tx  = tid & 7;           // 0..7  -> n = tx*8 + ...
    const int rdb = tx * 8 + ((tx >> 2) << 2);   // skewed B read base
    // loaders
    const int lrA = tid >> 1;          // 0..127
    const int lcA = (tid & 1) * 8;     // 0 or 8
    const int rnB = tid >> 2;          // 0..63
    const int lcB = (tid & 3) * 4;     // 0,4,8,12
    const int boB = bs_off(rnB);

    u64 acc[4][4];
#pragma unroll
    for (int i = 0; i < 4; i++)
#pragma unroll
        for (int j = 0; j < 4; j++) acc[i][j] = 0ull;

    const int nch = K / 16;
    float4 ra0, ra1, rb;

    // prologue: chunk 0
    ra0 = *(const float4*)(Ab + (size_t)lrA * K + lcA);
    ra1 = *(const float4*)(Ab + (size_t)lrA * K + lcA + 4);
    rb  = *(const float4*)(Bb + (size_t)rnB * K + lcB);
    {
        float av[8] = {ra0.x, ra0.y, ra0.z, ra0.w, ra1.x, ra1.y, ra1.z, ra1.w};
        float bv[4] = {rb.x, rb.y, rb.z, rb.w};
#pragma unroll
        for (int j = 0; j < 8; j++) As[0][lcA + j][lrA] = av[j];
#pragma unroll
        for (int j = 0; j < 4; j++) Bs[0][lcB + j][boB] = bv[j];
    }
    __syncthreads();

    for (int c = 0; c < nch; c++) {
        const int buf = c & 1;
        if (c + 1 < nch) {
            const int k0 = (c + 1) * 16;
            ra0 = *(const float4*)(Ab + (size_t)lrA * K + k0 + lcA);
            ra1 = *(const float4*)(Ab + (size_t)lrA * K + k0 + lcA + 4);
            rb  = *(const float4*)(Bb + (size_t)rnB * K + k0 + lcB);
        }

#pragma unroll
        for (int kk = 0; kk < 16; kk++) {
            float4 a = *(const float4*)&As[buf][kk][ty * 4];
            ulonglong2 b0 = *(const ulonglong2*)&Bs[buf][kk][rdb];
            ulonglong2 b1 = *(const ulonglong2*)&Bs[buf][kk][rdb + 4];
            u64 bb[4] = {b0.x, b0.y, b1.x, b1.y};
            float av[4] = {a.x, a.y, a.z, a.w};
#pragma unroll
            for (int i = 0; i < 4; i++) {
                u64 ai = pack2(av[i], av[i]);
#pragma unroll
                for (int j = 0; j < 4; j++) ffma2(acc[i][j], ai, bb[j]);
            }
        }

        if (c + 1 < nch) {
            const int nbuf = buf ^ 1;
            float av[8] = {ra0.x, ra0.y, ra0.z, ra0.w, ra1.x, ra1.y, ra1.z, ra1.w};
            float bv[4] = {rb.x, rb.y, rb.z, rb.w};
#pragma unroll
            for (int j = 0; j < 8; j++) As[nbuf][lcA + j][lrA] = av[j];
#pragma unroll
            for (int j = 0; j < 4; j++) Bs[nbuf][lcB + j][boB] = bv[j];
            __syncthreads();
        }
    }

    // epilogue: acc[i][j] = (C[m][n+2j], C[m][n+2j+1]), m = mb+ty*4+i
    const int mBase = mb + ty * 4;
    const int nBase = nb + tx * 8;
#pragma unroll
    for (int i = 0; i < 4; i++) {
        float o[8];
#pragma unroll
        for (int j = 0; j < 4; j++) unpack2(acc[i][j], o[j * 2], o[j * 2 + 1]);
        float* cp = C + (size_t)(mBase + i) * N + nBase;
        *(float4*)(cp)     = make_float4(o[0], o[1], o[2], o[3]);
        *(float4*)(cp + 4) = make_float4(o[4], o[5], o[6], o[7]);
    }
}

// Fused QKV projection: grid.x spans 64 col-blocks (32 Q | 16 K | 16 V)
__global__ __launch_bounds__(256, 3) void qkv_gemm(
        const float* __restrict__ x,
        const float* __restrict__ Wq, const float* __restrict__ Wk,
        const float* __restrict__ Wv,
        float* __restrict__ Cq, float* __restrict__ Ck, float* __restrict__ Cv)
{
    __shared__ float As[2][16][APAD];
    __shared__ float Bs[2][16][BPAD];

    const int mb = blockIdx.y * 128;
    const int xb = blockIdx.x;
    const float* W; float* C; int nb, N;
    if (xb < 32)      { W = Wq; C = Cq; nb = xb * 64;        N = NH  * HD; }
    else if (xb < 48) { W = Wk; C = Ck; nb = (xb - 32) * 64; N = NKV * HD; }
    else              { W = Wv; C = Cv; nb = (xb - 48) * 64; N = NKV * HD; }

    gemm_core(x + (size_t)mb * HID, W + (size_t)nb * HID, C, N, HID, mb, nb,
              As, Bs);
}

__global__ __launch_bounds__(256, 3) void sgemm_f32x2(
        const float* __restrict__ A, const float* __restrict__ Bw,
        float* __restrict__ C, int N, int K)
{
    __shared__ float As[2][16][APAD];
    __shared__ float Bs[2][16][BPAD];
    const int mb = blockIdx.y * 128;
    const int nb = blockIdx.x * 64;
    gemm_core(A + (size_t)mb * K, Bw + (size_t)nb * K, C, N, K, mb, nb, As, Bs);
}

// ---------------- fused RMSNorm + RoPE (q and k heads, one launch) ---------
__global__ __launch_bounds__(128) void rmsnorm_rope_kernel(
        float* __restrict__ qb, float* __restrict__ kb,
        const float* __restrict__ cosb, const float* __restrict__ sinb,
        const float* __restrict__ qw, const float* __restrict__ kw)
{
    const int idx  = blockIdx.x;
    const int head = idx % (NH + NKV);
    const int bl   = idx / (NH + NKV);
    const int d    = threadIdx.x;

    float* vec; const float* w;
    if (head < NH) { vec = qb + ((size_t)bl*NH  + head)      * HD; w = qw; }
    else           { vec = kb + ((size_t)bl*NKV + (head-NH)) * HD; w = kw; }

    float val = vec[d];
    float ss  = val * val;
#pragma unroll
    for (int o = 16; o > 0; o >>= 1) ss += __shfl_xor_sync(0xffffffffu, ss, o);
    __shared__ float wsum[4];
    if ((d & 31) == 0) wsum[d >> 5] = ss;
    __syncthreads();
    float tot = wsum[0] + wsum[1] + wsum[2] + wsum[3];
    float r   = rsqrtf(tot * (1.0f/HD) + 1e-6f);
    float nv  = val * r * w[d];

    __shared__ float sv[HD];
    sv[d] = nv;
    __syncthreads();

    const float* cp = cosb + (size_t)bl * HD;
    const float* sp = sinb + (size_t)bl * HD;
    float outv;
    if (d < 64) outv = nv * cp[d]    - sv[d+64] * sp[d];
    else        outv = nv * cp[d-64] + sv[d-64] * sp[d-64];
    vec[d] = outv;
}

// ---------------- flash attention (R11 — unchanged, best measured) ---------
#define AROW 160
__global__ __launch_bounds__(128) void attn_kernel(
        const float* __restrict__ Q, const float* __restrict__ Kb,
        const float* __restrict__ Vb, float* __restrict__ O)
{
    __shared__ float Ks[32][AROW];
    __shared__ float Vs[32][AROW];

    const int tid = threadIdx.x;
    const int hg  = tid >> 6;          // head group 0/1
    const int t2  = tid & 63;
    const int sub8 = t2 & 7;           // 16-dim segment
    const int qs  = t2 >> 3;           // 0..7
    const int b   = blockIdx.z;
    const int kvh = blockIdx.y;
    const int h   = kvh * 2 + hg;
    const int q0  = blockIdx.x * 32;

    int qrow[4];
#pragma unroll
    for (int e = 0; e < 4; e++) qrow[e] = q0 + qs + e * 8;

    const float scale = 0.08838834764831844f;   // 1/sqrt(128)
    u64 q2[4][8];
#pragma unroll
    for (int e = 0; e < 4; e++) {
        const float* qpp = Q + (((size_t)b*LSEQ + qrow[e])*NH + h)*HD + sub8*16;
#pragma unroll
        for (int j = 0; j < 8; j++) {
            float2 v = *(const float2*)(qpp + j*2);
            q2[e][j] = pack2(v.x * scale, v.y * scale);
        }
    }

    float l[4] = {0.f, 0.f, 0.f, 0.f};
    u64 acc[4][8];
#pragma unroll
    for (int e = 0; e < 4; e++)
#pragma unroll
        for (int j = 0; j < 8; j++) acc[e][j] = 0ull;

    const bool img = (q0 < NIMG);
    const int nk = img ? (LSEQ/32) : (q0/32 + 1);
    const int nfull = img ? nk : (q0/32);
    const int segoff = sub8 * 20;

    for (int t = 0; t < nk; t++) {
        const int k0 = t * 32;
        const size_t kbase = (((size_t)b*LSEQ + k0)*NKV + kvh)*HD;
#pragma unroll
        for (int i = 0; i < 8; i++) {
            int idx = tid + i*128;
            int row = idx >> 5;
            int c   = (idx & 31) << 2;
            int so  = row * AROW + (c >> 4) * 20 + (c & 15);
            size_t g = kbase + (size_t)row*NKV*HD + c;
            *(float4*)&Ks[0][so] = *(const float4*)(Kb + g);
            *(float4*)&Vs[0][so] = *(const float4*)(Vb + g);
        }
        __syncthreads();

        const bool need_mask = (t >= nfull);

#pragma unroll
        for (int kk = 0; kk < 32; kk++) {
            const ulonglong2* kr = (const ulonglong2*)&Ks[kk][segoff];
            ulonglong2 k01 = kr[0], k23 = kr[1], k45 = kr[2], k67 = kr[3];
            u64 kv[8] = {k01.x, k01.y, k23.x, k23.y, k45.x, k45.y, k67.x, k67.y};

            float p[4];
#pragma unroll
            for (int e = 0; e < 4; e++) {
                u64 p2 = 0ull;
#pragma unroll
                for (int j = 0; j < 8; j++) ffma2(p2, q2[e][j], kv[j]);
                float x, y;
                unpack2(p2, x, y);
                p[e] = x + y;
            }
#pragma unroll
            for (int e = 0; e < 4; e++) {
                p[e] += __shfl_xor_sync(0xffffffffu, p[e], 1);
                p[e] += __shfl_xor_sync(0xffffffffu, p[e], 2);
                p[e] += __shfl_xor_sync(0xffffffffu, p[e], 4);
            }

            float ee[4];
#pragma unroll
            for (int e = 0; e < 4; e++) {
                float ev = __expf(p[e] - 16.f);
                if (need_mask && (k0 + kk > qrow[e])) ev = 0.f;
                ee[e] = ev;
                l[e] += ev;
            }

            const ulonglong2* vr = (const ulonglong2*)&Vs[kk][segoff];
            ulonglong2 v01 = vr[0], v23 = vr[1], v45 = vr[2], v67 = vr[3];
            u64 vv[8] = {v01.x, v01.y, v23.x, v23.y, v45.x, v45.y, v67.x, v67.y};
#pragma unroll
            for (int e = 0; e < 4; e++) {
                u64 pe = pack2(ee[e], ee[e]);
#pragma unroll
                for (int j = 0; j < 8; j++) ffma2(acc[e][j], pe, vv[j]);
            }
        }
        __syncthreads();
    }

#pragma unroll
    for (int e = 0; e < 4; e++) {
        const float inv = 1.f / l[e];
        float* op = O + (((size_t)b*LSEQ + qrow[e])*NH + h)*HD + sub8*16;
#pragma unroll
        for (int j = 0; j < 4; j++) {
            float x, y, zx, zy;
            unpack2(acc[e][j*2],   x,  y);
            unpack2(acc[e][j*2+1], zx, zy);
            *(float4*)(op + j*4) = make_float4(x*inv, y*inv, zx*inv, zy*inv);
        }
    }
}

// ---------------- launch ----------------------------------------------------
// 4 launches; #4 (profiled) = Wo GEMM (the new core).
extern "C" void kernel_launch(void* const* d_in, const int* in_sizes, int n_in,
                              void* d_out, int out_size)
{
    const float* x    = (const float*)d_in[0];
    const float* cosb = (const float*)d_in[1];
    const float* sinb = (const float*)d_in[2];
    // d_in[3] = attention_mask (recomputed analytically, unused)
    const float* Wq   = (const float*)d_in[4];
    const float* Wk   = (const float*)d_in[5];
    const float* Wv   = (const float*)d_in[6];
    const float* Wo   = (const float*)d_in[7];
    const float* qw   = (const float*)d_in[8];
    const float* kw   = (const float*)d_in[9];
    float* out = (float*)d_out;

    float *gq, *gk, *gv, *gao;
    cudaGetSymbolAddress((void**)&gq,  g_q);
    cudaGetSymbolAddress((void**)&gk,  g_k);
    cudaGetSymbolAddress((void**)&gv,  g_v);
    cudaGetSymbolAddress((void**)&gao, g_ao);

    // 1: fused QKV projection (64 col-blocks x 32 row-blocks)
    qkv_gemm<<<dim3(64, MROWS/128), 256>>>(x, Wq, Wk, Wv, gq, gk, gv);

    // 2: RMSNorm + RoPE (combined q+k, one launch)
    rmsnorm_rope_kernel<<<BATCH*LSEQ*(NH+NKV), 128>>>(gq, gk, cosb, sinb, qw, kw);

    // 3: attention (R11 config)
    attn_kernel<<<dim3(LSEQ/32, NKV, BATCH), 128>>>(gq, gk, gv, gao);

    // 4: output projection (profiled slot — new GEMM core)
    sgemm_f32x2<<<dim3(HID/64, MROWS/128), 256>>>(gao, Wo, out, HID, NH*HD);
}

// round 13
// speedup vs baseline: 1.1268x; 1.1268x over previous
#include <cuda_runtime.h>
#include <cuda_bf16.h>
#include <cstdint>

// Problem constants
#define BATCH 2
#define LSEQ  2048
#define HID   2048
#define NH    16
#define NKV   8
#define HD    128
#define NIMG  1024
#define MROWS (BATCH*LSEQ)   // 4096

typedef unsigned long long u64;

// ---------------- scratch (device globals; no allocation allowed) ----------
__device__ float g_q [(size_t)BATCH*LSEQ*NH *HD];
__device__ float g_k [(size_t)BATCH*LSEQ*NKV*HD];
__device__ float g_v [(size_t)BATCH*LSEQ*NKV*HD];
__device__ float g_ao[(size_t)BATCH*LSEQ*NH *HD];

// ---------------- f32x2 helpers (Blackwell packed fp32, baseline PTX) ------
__device__ __forceinline__ void ffma2(u64& d, u64 a, u64 b) {
    asm("fma.rn.f32x2 %0, %1, %2, %0;" : "+l"(d) : "l"(a), "l"(b));
}
__device__ __forceinline__ u64 pack2(float x, float y) {
    u64 r; asm("mov.b64 %0, {%1, %2};" : "=l"(r) : "f"(x), "f"(y)); return r;
}
__device__ __forceinline__ void unpack2(u64 d, float& x, float& y) {
    asm("mov.b64 {%0, %1}, %2;" : "=f"(x), "=f"(y) : "l"(d));
}

// ---------------- GEMM core: 128x128 tile, BK=16, 128 thr, 16m x 8n --------
// C[m,n] = sum_k A[m,k]*B[n,k].
// Per kk per thread: 4 A-LDS.128 (2 distinct addrs/warp -> 1 wf each) +
// 2 B-LDS.128 (skewed, 16 quads 2-way -> 2 wf each) = 8 wf vs 64 FFMA2
// -> fma-issue is the sole binding pipe (LDS ~25% loaded).
// acc = 16m x 4 n-pairs (128 regs). 2 CTAs/SM.
#define APAD 132
#define BPAD 140
__device__ __forceinline__ int bs_off(int n) { return n + ((n >> 5) << 2); }

__device__ __forceinline__ void gemm_core(
        const float* __restrict__ Ab, const float* __restrict__ Bb,
        float* __restrict__ C, int N, int K, int mb, int nb,
        float (*As)[16][APAD], float (*Bs)[16][BPAD])
{
    const int tid = threadIdx.x;        // 0..127
    const int ty  = tid >> 4;           // 0..7  -> m = ty*16 + i
    const int tx  = tid & 15;           // 0..15 -> n = tx*8 + ...
    const int rdb = tx * 8 + ((tx >> 2) << 2);   // skewed B read base
    const int boB = bs_off(tid);        // loader: B row = tid

    u64 acc[16][4];
#pragma unroll
    for (int i = 0; i < 16; i++)
#pragma unroll
        for (int j = 0; j < 4; j++) acc[i][j] = 0ull;

    const int nch = K / 16;
    float4 ra[4], rb[4];

    // prologue: chunk 0 (thread loads row 'tid' of A and B, 16 k each)
    {
        const float* ap = Ab + (size_t)tid * K;
        const float* bp = Bb + (size_t)tid * K;
#pragma unroll
        for (int i = 0; i < 4; i++) {
            ra[i] = *(const float4*)(ap + i * 4);
            rb[i] = *(const float4*)(bp + i * 4);
        }
#pragma unroll
        for (int i = 0; i < 4; i++) {
            float av[4] = {ra[i].x, ra[i].y, ra[i].z, ra[i].w};
            float bv[4] = {rb[i].x, rb[i].y, rb[i].z, rb[i].w};
#pragma unroll
            for (int j = 0; j < 4; j++) {
                As[0][i * 4 + j][tid] = av[j];
                Bs[0][i * 4 + j][boB] = bv[j];
            }
        }
    }
    __syncthreads();

    for (int c = 0; c < nch; c++) {
        const int buf = c & 1;
        if (c + 1 < nch) {
            const int k0 = (c + 1) * 16;
            const float* ap = Ab + (size_t)tid * K + k0;
            const float* bp = Bb + (size_t)tid * K + k0;
#pragma unroll
            for (int i = 0; i < 4; i++) {
                ra[i] = *(const float4*)(ap + i * 4);
                rb[i] = *(const float4*)(bp + i * 4);
            }
        }

#pragma unroll
        for (int kk = 0; kk < 16; kk++) {
            float4 a0 = *(const float4*)&As[buf][kk][ty * 16];
            float4 a1 = *(const float4*)&As[buf][kk][ty * 16 + 4];
            float4 a2 = *(const float4*)&As[buf][kk][ty * 16 + 8];
            float4 a3 = *(const float4*)&As[buf][kk][ty * 16 + 12];
            ulonglong2 b0 = *(const ulonglong2*)&Bs[buf][kk][rdb];
            ulonglong2 b1 = *(const ulonglong2*)&Bs[buf][kk][rdb + 4];
            u64 bb[4] = {b0.x, b0.y, b1.x, b1.y};
            float av[16] = {a0.x, a0.y, a0.z, a0.w, a1.x, a1.y, a1.z, a1.w,
                            a2.x, a2.y, a2.z, a2.w, a3.x, a3.y, a3.z, a3.w};
#pragma unroll
            for (int i = 0; i < 16; i++) {
                u64 ai = pack2(av[i], av[i]);
#pragma unroll
                for (int j = 0; j < 4; j++) ffma2(acc[i][j], ai, bb[j]);
            }
        }

        if (c + 1 < nch) {
            const int nbuf = buf ^ 1;
#pragma unroll
            for (int i = 0; i < 4; i++) {
                float av[4] = {ra[i].x, ra[i].y, ra[i].z, ra[i].w};
                float bv[4] = {rb[i].x, rb[i].y, rb[i].z, rb[i].w};
#pragma unroll
                for (int j = 0; j < 4; j++) {
                    As[nbuf][i * 4 + j][tid] = av[j];
                    Bs[nbuf][i * 4 + j][boB] = bv[j];
                }
            }
            __syncthreads();
        }
    }

    // epilogue: acc[i][j] = (C[m][n+2j], C[m][n+2j+1]), m = mb+ty*16+i
    const int mBase = mb + ty * 16;
    const int nBase = nb + tx * 8;
#pragma unroll
    for (int i = 0; i < 16; i++) {
        float o[8];
#pragma unroll
        for (int j = 0; j < 4; j++) unpack2(acc[i][j], o[j * 2], o[j * 2 + 1]);
        float* cp = C + (size_t)(mBase + i) * N + nBase;
        *(float4*)(cp)     = make_float4(o[0], o[1], o[2], o[3]);
        *(float4*)(cp + 4) = make_float4(o[4], o[5], o[6], o[7]);
    }
}

// Fused QKV projection: grid.x spans 32 col-blocks (16 Q | 8 K | 8 V)
__global__ __launch_bounds__(128, 2) void qkv_gemm(
        const float* __restrict__ x,
        const float* __restrict__ Wq, const float* __restrict__ Wk,
        const float* __restrict__ Wv,
        float* __restrict__ Cq, float* __restrict__ Ck, float* __restrict__ Cv)
{
    __shared__ float As[2][16][APAD];
    __shared__ float Bs[2][16][BPAD];

    const int mb = blockIdx.y * 128;
    const int xb = blockIdx.x;
    const float* W; float* C; int nb, N;
    if (xb < 16)      { W = Wq; C = Cq; nb = xb * 128;        N = NH  * HD; }
    else if (xb < 24) { W = Wk; C = Ck; nb = (xb - 16) * 128; N = NKV * HD; }
    else              { W = Wv; C = Cv; nb = (xb - 24) * 128; N = NKV * HD; }

    gemm_core(x + (size_t)mb * HID, W + (size_t)nb * HID, C, N, HID, mb, nb,
              As, Bs);
}

__global__ __launch_bounds__(128, 2) void sgemm_f32x2(
        const float* __restrict__ A, const float* __restrict__ Bw,
        float* __restrict__ C, int N, int K)
{
    __shared__ float As[2][16][APAD];
    __shared__ float Bs[2][16][BPAD];
    const int mb = blockIdx.y * 128;
    const int nb = blockIdx.x * 128;
    gemm_core(A + (size_t)mb * K, Bw + (size_t)nb * K, C, N, K, mb, nb, As, Bs);
}

// ---------------- fused RMSNorm + RoPE (q and k heads, one launch) ---------
__global__ __launch_bounds__(128) void rmsnorm_rope_kernel(
        float* __restrict__ qb, float* __restrict__ kb,
        const float* __restrict__ cosb, const float* __restrict__ sinb,
        const float* __restrict__ qw, const float* __restrict__ kw)
{
    const int idx  = blockIdx.x;
    const int head = idx % (NH + NKV);
    const int bl   = idx / (NH + NKV);
    const int d    = threadIdx.x;

    float* vec; const float* w;
    if (head < NH) { vec = qb + ((size_t)bl*NH  + head)      * HD; w = qw; }
    else           { vec = kb + ((size_t)bl*NKV + (head-NH)) * HD; w = kw; }

    float val = vec[d];
    float ss  = val * val;
#pragma unroll
    for (int o = 16; o > 0; o >>= 1) ss += __shfl_xor_sync(0xffffffffu, ss, o);
    __shared__ float wsum[4];
    if ((d & 31) == 0) wsum[d >> 5] = ss;
    __syncthreads();
    float tot = wsum[0] + wsum[1] + wsum[2] + wsum[3];
    float r   = rsqrtf(tot * (1.0f/HD) + 1e-6f);
    float nv  = val * r * w[d];

    __shared__ float sv[HD];
    sv[d] = nv;
    __syncthreads();

    const float* cp = cosb + (size_t)bl * HD;
    const float* sp = sinb + (size_t)bl * HD;
    float outv;
    if (d < 64) outv = nv * cp[d]    - sv[d+64] * sp[d];
    else        outv = nv * cp[d-64] + sv[d-64] * sp[d-64];
    vec[d] = outv;
}

// ---------------- flash attention (R11 — unchanged, best measured) ---------
#define AROW 160
__global__ __launch_bounds__(128) void attn_kernel(
        const float* __restrict__ Q, const float* __restrict__ Kb,
        const float* __restrict__ Vb, float* __restrict__ O)
{
    __shared__ float Ks[32][AROW];
    __shared__ float Vs[32][AROW];

    const int tid = threadIdx.x;
    const int hg  = tid >> 6;          // head group 0/1
    const int t2  = tid & 63;
    const int sub8 = t2 & 7;           // 16-dim segment
    const int qs  = t2 >> 3;           // 0..7
    const int b   = blockIdx.z;
    const int kvh = blockIdx.y;
    const int h   = kvh * 2 + hg;
    const int q0  = blockIdx.x * 32;

    int qrow[4];
#pragma unroll
    for (int e = 0; e < 4; e++) qrow[e] = q0 + qs + e * 8;

    const float scale = 0.08838834764831844f;   // 1/sqrt(128)
    u64 q2[4][8];
#pragma unroll
    for (int e = 0; e < 4; e++) {
        const float* qpp = Q + (((size_t)b*LSEQ + qrow[e])*NH + h)*HD + sub8*16;
#pragma unroll
        for (int j = 0; j < 8; j++) {
            float2 v = *(const float2*)(qpp + j*2);
            q2[e][j] = pack2(v.x * scale, v.y * scale);
        }
    }

    float l[4] = {0.f, 0.f, 0.f, 0.f};
    u64 acc[4][8];
#pragma unroll
    for (int e = 0; e < 4; e++)
#pragma unroll
        for (int j = 0; j < 8; j++) acc[e][j] = 0ull;

    const bool img = (q0 < NIMG);
    const int nk = img ? (LSEQ/32) : (q0/32 + 1);
    const int nfull = img ? nk : (q0/32);
    const int segoff = sub8 * 20;

    for (int t = 0; t < nk; t++) {
        const int k0 = t * 32;
        const size_t kbase = (((size_t)b*LSEQ + k0)*NKV + kvh)*HD;
#pragma unroll
        for (int i = 0; i < 8; i++) {
            int idx = tid + i*128;
            int row = idx >> 5;
            int c   = (idx & 31) << 2;
            int so  = row * AROW + (c >> 4) * 20 + (c & 15);
            size_t g = kbase + (size_t)row*NKV*HD + c;
            *(float4*)&Ks[0][so] = *(const float4*)(Kb + g);
            *(float4*)&Vs[0][so] = *(const float4*)(Vb + g);
        }
        __syncthreads();

        const bool need_mask = (t >= nfull);

#pragma unroll
        for (int kk = 0; kk < 32; kk++) {
            const ulonglong2* kr = (const ulonglong2*)&Ks[kk][segoff];
            ulonglong2 k01 = kr[0], k23 = kr[1], k45 = kr[2], k67 = kr[3];
            u64 kv[8] = {k01.x, k01.y, k23.x, k23.y, k45.x, k45.y, k67.x, k67.y};

            float p[4];
#pragma unroll
            for (int e = 0; e < 4; e++) {
                u64 p2 = 0ull;
#pragma unroll
                for (int j = 0; j < 8; j++) ffma2(p2, q2[e][j], kv[j]);
                float x, y;
                unpack2(p2, x, y);
                p[e] = x + y;
            }
#pragma unroll
            for (int e = 0; e < 4; e++) {
                p[e] += __shfl_xor_sync(0xffffffffu, p[e], 1);
                p[e] += __shfl_xor_sync(0xffffffffu, p[e], 2);
                p[e] += __shfl_xor_sync(0xffffffffu, p[e], 4);
            }

            float ee[4];
#pragma unroll
            for (int e = 0; e < 4; e++) {
                float ev = __expf(p[e] - 16.f);
                if (need_mask && (k0 + kk > qrow[e])) ev = 0.f;
                ee[e] = ev;
                l[e] += ev;
            }

            const ulonglong2* vr = (const ulonglong2*)&Vs[kk][segoff];
            ulonglong2 v01 = vr[0], v23 = vr[1], v45 = vr[2], v67 = vr[3];
            u64 vv[8] = {v01.x, v01.y, v23.x, v23.y, v45.x, v45.y, v67.x, v67.y};
#pragma unroll
            for (int e = 0; e < 4; e++) {
                u64 pe = pack2(ee[e], ee[e]);
#pragma unroll
                for (int j = 0; j < 8; j++) ffma2(acc[e][j], pe, vv[j]);
            }
        }
        __syncthreads();
    }

#pragma unroll
    for (int e = 0; e < 4; e++) {
        const float inv = 1.f / l[e];
        float* op = O + (((size_t)b*LSEQ + qrow[e])*NH + h)*HD + sub8*16;
#pragma unroll
        for (int j = 0; j < 4; j++) {
            float x, y, zx, zy;
            unpack2(acc[e][j*2],   x,  y);
            unpack2(acc[e][j*2+1], zx, zy);
            *(float4*)(op + j*4) = make_float4(x*inv, y*inv, zx*inv, zy*inv);
        }
    }
}

// ---------------- launch ----------------------------------------------------
// 4 launches; #4 (profiled) = Wo GEMM (the new 16x8 core).
extern "C" void kernel_launch(void* const* d_in, const int* in_sizes, int n_in,
                              void* d_out, int out_size)
{
    const float* x    = (const float*)d_in[0];
    const float* cosb = (const float*)d_in[1];
    const float* sinb = (const float*)d_in[2];
    // d_in[3] = attention_mask (recomputed analytically, unused)
    const float* Wq   = (const float*)d_in[4];
    const float* Wk   = (const float*)d_in[5];
    const float* Wv   = (const float*)d_in[6];
    const float* Wo   = (const float*)d_in[7];
    const float* qw   = (const float*)d_in[8];
    const float* kw   = (const float*)d_in[9];
    float* out = (float*)d_out;

    float *gq, *gk, *gv, *gao;
    cudaGetSymbolAddress((void**)&gq,  g_q);
    cudaGetSymbolAddress((void**)&gk,  g_k);
    cudaGetSymbolAddress((void**)&gv,  g_v);
    cudaGetSymbolAddress((void**)&gao, g_ao);

    // 1: fused QKV projection (32 col-blocks x 32 row-blocks)
    qkv_gemm<<<dim3(32, MROWS/128), 128>>>(x, Wq, Wk, Wv, gq, gk, gv);

    // 2: RMSNorm + RoPE (combined q+k, one launch)
    rmsnorm_rope_kernel<<<BATCH*LSEQ*(NH+NKV), 128>>>(gq, gk, cosb, sinb, qw, kw);

    // 3: attention (R11 config)
    attn_kernel<<<dim3(LSEQ/32, NKV, BATCH), 128>>>(gq, gk, gv, gao);

    // 4: output projection (profiled slot — new GEMM core)
    sgemm_f32x2<<<dim3(HID/128, MROWS/128), 128>>>(gao, Wo, out, HID, NH*HD);
}

// round 14
// speedup vs baseline: 1.1384x; 1.0103x over previous
#include <cuda_runtime.h>
#include <cuda_bf16.h>
#include <cstdint>

// Problem constants
#define BATCH 2
#define LSEQ  2048
#define HID   2048
#define NH    16
#define NKV   8
#define HD    128
#define NIMG  1024
#define MROWS (BATCH*LSEQ)   // 4096

typedef unsigned long long u64;

// ---------------- scratch (device globals; no allocation allowed) ----------
__device__ float g_q [(size_t)BATCH*LSEQ*NH *HD];
__device__ float g_k [(size_t)BATCH*LSEQ*NKV*HD];
__device__ float g_v [(size_t)BATCH*LSEQ*NKV*HD];
__device__ float g_ao[(size_t)BATCH*LSEQ*NH *HD];

// ---------------- f32x2 helpers (Blackwell packed fp32, baseline PTX) ------
__device__ __forceinline__ void ffma2(u64& d, u64 a, u64 b) {
    asm("fma.rn.f32x2 %0, %1, %2, %0;" : "+l"(d) : "l"(a), "l"(b));
}
__device__ __forceinline__ u64 pack2(float x, float y) {
    u64 r; asm("mov.b64 %0, {%1, %2};" : "=l"(r) : "f"(x), "f"(y)); return r;
}
__device__ __forceinline__ void unpack2(u64 d, float& x, float& y) {
    asm("mov.b64 {%0, %1}, %2;" : "=f"(x), "=f"(y) : "l"(d));
}

// ---------------- GEMM core (R11 — best measured) ---------------------------
// C[m,n] = sum_k A[m,k]*B[n,k]. 128x128 tile, BK=16, 256 threads, 8x8/thread.
// B segment tx stored at 8tx+4(tx>>2): 16 distinct 16B read addrs -> 2-way.
#define GPAD 140
__device__ __forceinline__ int bs_off(int n) { return n + ((n >> 5) << 2); }

__device__ __forceinline__ void gemm_core(
        const float* __restrict__ Ab, const float* __restrict__ Bb,
        float* __restrict__ C, int N, int K, int mb, int nb,
        float (*As)[16][GPAD], float (*Bs)[16][GPAD])
{
    const int tid = threadIdx.x;
    const int tx  = tid & 15;
    const int ty  = tid >> 4;
    const int lr  = tid >> 2;
    const int lc  = (tid & 3) * 4;

    u64 acc[8][4];
#pragma unroll
    for (int i = 0; i < 8; i++)
#pragma unroll
        for (int j = 0; j < 4; j++) acc[i][j] = 0ull;

    const int nch = K / 16;
    const int bo0 = bs_off(lr);
    const int bo1 = bs_off(lr + 64);
    const int rdb = tx * 8 + ((tx >> 2) << 2);
    float4 ra0, ra1, rb0, rb1;

    ra0 = *(const float4*)(Ab + (size_t)lr * K + lc);
    ra1 = *(const float4*)(Ab + (size_t)(lr + 64) * K + lc);
    rb0 = *(const float4*)(Bb + (size_t)lr * K + lc);
    rb1 = *(const float4*)(Bb + (size_t)(lr + 64) * K + lc);
    {
        float av0[4] = {ra0.x, ra0.y, ra0.z, ra0.w};
        float av1[4] = {ra1.x, ra1.y, ra1.z, ra1.w};
        float bv0[4] = {rb0.x, rb0.y, rb0.z, rb0.w};
        float bv1[4] = {rb1.x, rb1.y, rb1.z, rb1.w};
#pragma unroll
        for (int j = 0; j < 4; j++) {
            As[0][lc + j][lr]      = av0[j];
            As[0][lc + j][lr + 64] = av1[j];
            Bs[0][lc + j][bo0]     = bv0[j];
            Bs[0][lc + j][bo1]     = bv1[j];
        }
    }
    __syncthreads();

    for (int c = 0; c < nch; c++) {
        const int buf = c & 1;
        if (c + 1 < nch) {
            const int k0 = (c + 1) * 16;
            ra0 = *(const float4*)(Ab + (size_t)lr * K + k0 + lc);
            ra1 = *(const float4*)(Ab + (size_t)(lr + 64) * K + k0 + lc);
            rb0 = *(const float4*)(Bb + (size_t)lr * K + k0 + lc);
            rb1 = *(const float4*)(Bb + (size_t)(lr + 64) * K + k0 + lc);
        }

#pragma unroll
        for (int kk = 0; kk < 16; kk++) {
            float4 a0 = *(const float4*)&As[buf][kk][ty * 8];
            float4 a1 = *(const float4*)&As[buf][kk][ty * 8 + 4];
            ulonglong2 b0 = *(const ulonglong2*)&Bs[buf][kk][rdb];
            ulonglong2 b1 = *(const ulonglong2*)&Bs[buf][kk][rdb + 4];
            u64 bb[4] = {b0.x, b0.y, b1.x, b1.y};
            float av[8] = {a0.x, a0.y, a0.z, a0.w, a1.x, a1.y, a1.z, a1.w};
#pragma unroll
            for (int i = 0; i < 8; i++) {
                u64 ai = pack2(av[i], av[i]);
#pragma unroll
                for (int j = 0; j < 4; j++) ffma2(acc[i][j], ai, bb[j]);
            }
        }

        if (c + 1 < nch) {
            const int nbuf = buf ^ 1;
            float av0[4] = {ra0.x, ra0.y, ra0.z, ra0.w};
            float av1[4] = {ra1.x, ra1.y, ra1.z, ra1.w};
            float bv0[4] = {rb0.x, rb0.y, rb0.z, rb0.w};
            float bv1[4] = {rb1.x, rb1.y, rb1.z, rb1.w};
#pragma unroll
            for (int j = 0; j < 4; j++) {
                As[nbuf][lc + j][lr]      = av0[j];
                As[nbuf][lc + j][lr + 64] = av1[j];
                Bs[nbuf][lc + j][bo0]     = bv0[j];
                Bs[nbuf][lc + j][bo1]     = bv1[j];
            }
            __syncthreads();
        }
    }

    const int mBase = mb + ty * 8;
    const int nBase = nb + tx * 8;
#pragma unroll
    for (int i = 0; i < 8; i++) {
        float o[8];
#pragma unroll
        for (int j = 0; j < 4; j++) unpack2(acc[i][j], o[j * 2], o[j * 2 + 1]);
        float* cp = C + (size_t)(mBase + i) * N + nBase;
        *(float4*)(cp)     = make_float4(o[0], o[1], o[2], o[3]);
        *(float4*)(cp + 4) = make_float4(o[4], o[5], o[6], o[7]);
    }
}

// Fused QKV projection: grid.x spans 32 col-blocks (16 Q | 8 K | 8 V)
__global__ __launch_bounds__(256) void qkv_gemm(
        const float* __restrict__ x,
        const float* __restrict__ Wq, const float* __restrict__ Wk,
        const float* __restrict__ Wv,
        float* __restrict__ Cq, float* __restrict__ Ck, float* __restrict__ Cv)
{
    __shared__ float As[2][16][GPAD];
    __shared__ float Bs[2][16][GPAD];

    const int mb = blockIdx.y * 128;
    const int xb = blockIdx.x;
    const float* W; float* C; int nb, N;
    if (xb < 16)      { W = Wq; C = Cq; nb = xb * 128;        N = NH  * HD; }
    else if (xb < 24) { W = Wk; C = Ck; nb = (xb - 16) * 128; N = NKV * HD; }
    else              { W = Wv; C = Cv; nb = (xb - 24) * 128; N = NKV * HD; }

    gemm_core(x + (size_t)mb * HID, W + (size_t)nb * HID, C, N, HID, mb, nb,
              As, Bs);
}

__global__ __launch_bounds__(256) void sgemm_f32x2(
        const float* __restrict__ A, const float* __restrict__ Bw,
        float* __restrict__ C, int N, int K)
{
    __shared__ float As[2][16][GPAD];
    __shared__ float Bs[2][16][GPAD];
    const int mb = blockIdx.y * 128;
    const int nb = blockIdx.x * 128;
    gemm_core(A + (size_t)mb * K, Bw + (size_t)nb * K, C, N, K, mb, nb, As, Bs);
}

// ---------------- fused RMSNorm + RoPE (generic head count) ----------------
__global__ __launch_bounds__(128) void rmsnorm_rope_kernel(
        float* __restrict__ base, int heads,
        const float* __restrict__ cosb, const float* __restrict__ sinb,
        const float* __restrict__ w)
{
    const int idx  = blockIdx.x;
    const int head = idx % heads;
    const int bl   = idx / heads;
    const int d    = threadIdx.x;

    float* vec = base + ((size_t)bl * heads + head) * HD;

    float val = vec[d];
    float ss  = val * val;
#pragma unroll
    for (int o = 16; o > 0; o >>= 1) ss += __shfl_xor_sync(0xffffffffu, ss, o);
    __shared__ float wsum[4];
    if ((d & 31) == 0) wsum[d >> 5] = ss;
    __syncthreads();
    float tot = wsum[0] + wsum[1] + wsum[2] + wsum[3];
    float r   = rsqrtf(tot * (1.0f/HD) + 1e-6f);
    float nv  = val * r * w[d];

    __shared__ float sv[HD];
    sv[d] = nv;
    __syncthreads();

    const float* cp = cosb + (size_t)bl * HD;
    const float* sp = sinb + (size_t)bl * HD;
    float outv;
    if (d < 64) outv = nv * cp[d]    - sv[d+64] * sp[d];
    else        outv = nv * cp[d-64] + sv[d-64] * sp[d-64];
    vec[d] = outv;
}

// ---------------- flash attention: 16 dims/lane, 2 queries/thread ----------
// CTA = (b, kvh, q-block of 16), 128 threads. hg = tid>>6 -> head 2*kvh+hg.
// Within a head-group (64 thr): sub8 = t2&7 owns dims sub8*16..+16;
// qs = t2>>3 owns queries q0+qs, q0+qs+8. Half the regs of R11 (q2+acc =
// 64 regs, ~110 total) -> 3-4 CTAs/SM (vs 2) for latency hiding.
// Conflict-free smem (segment s at s*20). Fixed-offset softmax (exp(p-16)).
#define AROW 160
__global__ __launch_bounds__(128, 4) void attn_kernel(
        const float* __restrict__ Q, const float* __restrict__ Kb,
        const float* __restrict__ Vb, float* __restrict__ O)
{
    __shared__ float Ks[32][AROW];
    __shared__ float Vs[32][AROW];

    const int tid = threadIdx.x;
    const int hg  = tid >> 6;          // head group 0/1
    const int t2  = tid & 63;
    const int sub8 = t2 & 7;           // 16-dim segment
    const int qs  = t2 >> 3;           // 0..7
    const int b   = blockIdx.z;
    const int kvh = blockIdx.y;
    const int h   = kvh * 2 + hg;
    const int q0  = blockIdx.x * 16;

    int qrow[2];
#pragma unroll
    for (int e = 0; e < 2; e++) qrow[e] = q0 + qs + e * 8;

    const float scale = 0.08838834764831844f;   // 1/sqrt(128)
    u64 q2[2][8];
#pragma unroll
    for (int e = 0; e < 2; e++) {
        const float* qpp = Q + (((size_t)b*LSEQ + qrow[e])*NH + h)*HD + sub8*16;
#pragma unroll
        for (int j = 0; j < 8; j++) {
            float2 v = *(const float2*)(qpp + j*2);
            q2[e][j] = pack2(v.x * scale, v.y * scale);
        }
    }

    float l[2] = {0.f, 0.f};
    u64 acc[2][8];
#pragma unroll
    for (int e = 0; e < 2; e++)
#pragma unroll
        for (int j = 0; j < 8; j++) acc[e][j] = 0ull;

    const bool img = (q0 < NIMG);
    const int nk = img ? (LSEQ/32) : (q0/32 + 1);
    const int nfull = img ? nk : (q0/32);
    const int segoff = sub8 * 20;

    for (int t = 0; t < nk; t++) {
        const int k0 = t * 32;
        const size_t kbase = (((size_t)b*LSEQ + k0)*NKV + kvh)*HD;
#pragma unroll
        for (int i = 0; i < 8; i++) {
            int idx = tid + i*128;
            int row = idx >> 5;
            int c   = (idx & 31) << 2;
            int so  = row * AROW + (c >> 4) * 20 + (c & 15);
            size_t g = kbase + (size_t)row*NKV*HD + c;
            *(float4*)&Ks[0][so] = *(const float4*)(Kb + g);
            *(float4*)&Vs[0][so] = *(const float4*)(Vb + g);
        }
        __syncthreads();

        const bool need_mask = (t >= nfull);

#pragma unroll
        for (int kk = 0; kk < 32; kk++) {
            const ulonglong2* kr = (const ulonglong2*)&Ks[kk][segoff];
            ulonglong2 k01 = kr[0], k23 = kr[1], k45 = kr[2], k67 = kr[3];
            u64 kv[8] = {k01.x, k01.y, k23.x, k23.y, k45.x, k45.y, k67.x, k67.y};

            float p[2];
#pragma unroll
            for (int e = 0; e < 2; e++) {
                u64 p2 = 0ull;
#pragma unroll
                for (int j = 0; j < 8; j++) ffma2(p2, q2[e][j], kv[j]);
                float x, y;
                unpack2(p2, x, y);
                p[e] = x + y;
            }
#pragma unroll
            for (int e = 0; e < 2; e++) {
                p[e] += __shfl_xor_sync(0xffffffffu, p[e], 1);
                p[e] += __shfl_xor_sync(0xffffffffu, p[e], 2);
                p[e] += __shfl_xor_sync(0xffffffffu, p[e], 4);
            }

            float ee[2];
#pragma unroll
            for (int e = 0; e < 2; e++) {
                float ev = __expf(p[e] - 16.f);
                if (need_mask && (k0 + kk > qrow[e])) ev = 0.f;
                ee[e] = ev;
                l[e] += ev;
            }

            const ulonglong2* vr = (const ulonglong2*)&Vs[kk][segoff];
            ulonglong2 v01 = vr[0], v23 = vr[1], v45 = vr[2], v67 = vr[3];
            u64 vv[8] = {v01.x, v01.y, v23.x, v23.y, v45.x, v45.y, v67.x, v67.y};
#pragma unroll
            for (int e = 0; e < 2; e++) {
                u64 pe = pack2(ee[e], ee[e]);
#pragma unroll
                for (int j = 0; j < 8; j++) ffma2(acc[e][j], pe, vv[j]);
            }
        }
        __syncthreads();
    }

#pragma unroll
    for (int e = 0; e < 2; e++) {
        const float inv = 1.f / l[e];
        float* op = O + (((size_t)b*LSEQ + qrow[e])*NH + h)*HD + sub8*16;
#pragma unroll
        for (int j = 0; j < 4; j++) {
            float x, y, zx, zy;
            unpack2(acc[e][j*2],   x,  y);
            unpack2(acc[e][j*2+1], zx, zy);
            *(float4*)(op + j*4) = make_float4(x*inv, y*inv, zx*inv, zy*inv);
        }
    }
}

// ---------------- launch ----------------------------------------------------
// 5 launches; #4 (profiled) = attention.
extern "C" void kernel_launch(void* const* d_in, const int* in_sizes, int n_in,
                              void* d_out, int out_size)
{
    const float* x    = (const float*)d_in[0];
    const float* cosb = (const float*)d_in[1];
    const float* sinb = (const float*)d_in[2];
    // d_in[3] = attention_mask (recomputed analytically, unused)
    const float* Wq   = (const float*)d_in[4];
    const float* Wk   = (const float*)d_in[5];
    const float* Wv   = (const float*)d_in[6];
    const float* Wo   = (const float*)d_in[7];
    const float* qw   = (const float*)d_in[8];
    const float* kw   = (const float*)d_in[9];
    float* out = (float*)d_out;

    float *gq, *gk, *gv, *gao;
    cudaGetSymbolAddress((void**)&gq,  g_q);
    cudaGetSymbolAddress((void**)&gk,  g_k);
    cudaGetSymbolAddress((void**)&gv,  g_v);
    cudaGetSymbolAddress((void**)&gao, g_ao);

    // 1: fused QKV projection
    qkv_gemm<<<dim3(32, MROWS/128), 256>>>(x, Wq, Wk, Wv, gq, gk, gv);

    // 2,3: RMSNorm + RoPE
    rmsnorm_rope_kernel<<<BATCH*LSEQ*NH,  128>>>(gq, NH,  cosb, sinb, qw);
    rmsnorm_rope_kernel<<<BATCH*LSEQ*NKV, 128>>>(gk, NKV, cosb, sinb, kw);

    // 4: attention (profiled slot) — 16-query blocks, 2 q/thread
    attn_kernel<<<dim3(LSEQ/16, NKV, BATCH), 128>>>(gq, gk, gv, gao);

    // 5: output projection
    sgemm_f32x2<<<dim3(HID/128, MROWS/128), 256>>>(gao, Wo, out, HID, NH*HD);
}

// round 15
// speedup vs baseline: 1.3373x; 1.1747x over previous
#include <cuda_runtime.h>
#include <cuda_bf16.h>
#include <cstdint>

// Problem constants
#define BATCH 2
#define LSEQ  2048
#define HID   2048
#define NH    16
#define NKV   8
#define HD    128
#define NIMG  1024
#define MROWS (BATCH*LSEQ)   // 4096

typedef unsigned long long u64;

// ---------------- scratch (device globals; no allocation allowed) ----------
__device__ float g_q [(size_t)BATCH*LSEQ*NH *HD];
__device__ float g_k [(size_t)BATCH*LSEQ*NKV*HD];
__device__ float g_v [(size_t)BATCH*LSEQ*NKV*HD];
__device__ float g_ao[(size_t)BATCH*LSEQ*NH *HD];

// ---------------- f32x2 helpers (Blackwell packed fp32, baseline PTX) ------
__device__ __forceinline__ void ffma2(u64& d, u64 a, u64 b) {
    asm("fma.rn.f32x2 %0, %1, %2, %0;" : "+l"(d) : "l"(a), "l"(b));
}
__device__ __forceinline__ u64 pack2(float x, float y) {
    u64 r; asm("mov.b64 %0, {%1, %2};" : "=l"(r) : "f"(x), "f"(y)); return r;
}
__device__ __forceinline__ void unpack2(u64 d, float& x, float& y) {
    asm("mov.b64 {%0, %1}, %2;" : "=f"(x), "=f"(y) : "l"(d));
}

// ---------------- GEMM core (R11 — best measured) ---------------------------
// C[m,n] = sum_k A[m,k]*B[n,k]. 128x128 tile, BK=16, 256 threads, 8x8/thread.
// B segment tx stored at 8tx+4(tx>>2): 16 distinct 16B read addrs -> 2-way.
#define GPAD 140
__device__ __forceinline__ int bs_off(int n) { return n + ((n >> 5) << 2); }

__device__ __forceinline__ void gemm_core(
        const float* __restrict__ Ab, const float* __restrict__ Bb,
        float* __restrict__ C, int N, int K, int mb, int nb,
        float (*As)[16][GPAD], float (*Bs)[16][GPAD])
{
    const int tid = threadIdx.x;
    const int tx  = tid & 15;
    const int ty  = tid >> 4;
    const int lr  = tid >> 2;
    const int lc  = (tid & 3) * 4;

    u64 acc[8][4];
#pragma unroll
    for (int i = 0; i < 8; i++)
#pragma unroll
        for (int j = 0; j < 4; j++) acc[i][j] = 0ull;

    const int nch = K / 16;
    const int bo0 = bs_off(lr);
    const int bo1 = bs_off(lr + 64);
    const int rdb = tx * 8 + ((tx >> 2) << 2);
    float4 ra0, ra1, rb0, rb1;

    ra0 = *(const float4*)(Ab + (size_t)lr * K + lc);
    ra1 = *(const float4*)(Ab + (size_t)(lr + 64) * K + lc);
    rb0 = *(const float4*)(Bb + (size_t)lr * K + lc);
    rb1 = *(const float4*)(Bb + (size_t)(lr + 64) * K + lc);
    {
        float av0[4] = {ra0.x, ra0.y, ra0.z, ra0.w};
        float av1[4] = {ra1.x, ra1.y, ra1.z, ra1.w};
        float bv0[4] = {rb0.x, rb0.y, rb0.z, rb0.w};
        float bv1[4] = {rb1.x, rb1.y, rb1.z, rb1.w};
#pragma unroll
        for (int j = 0; j < 4; j++) {
            As[0][lc + j][lr]      = av0[j];
            As[0][lc + j][lr + 64] = av1[j];
            Bs[0][lc + j][bo0]     = bv0[j];
            Bs[0][lc + j][bo1]     = bv1[j];
        }
    }
    __syncthreads();

    for (int c = 0; c < nch; c++) {
        const int buf = c & 1;
        if (c + 1 < nch) {
            const int k0 = (c + 1) * 16;
            ra0 = *(const float4*)(Ab + (size_t)lr * K + k0 + lc);
            ra1 = *(const float4*)(Ab + (size_t)(lr + 64) * K + k0 + lc);
            rb0 = *(const float4*)(Bb + (size_t)lr * K + k0 + lc);
            rb1 = *(const float4*)(Bb + (size_t)(lr + 64) * K + k0 + lc);
        }

#pragma unroll
        for (int kk = 0; kk < 16; kk++) {
            float4 a0 = *(const float4*)&As[buf][kk][ty * 8];
            float4 a1 = *(const float4*)&As[buf][kk][ty * 8 + 4];
            ulonglong2 b0 = *(const ulonglong2*)&Bs[buf][kk][rdb];
            ulonglong2 b1 = *(const ulonglong2*)&Bs[buf][kk][rdb + 4];
            u64 bb[4] = {b0.x, b0.y, b1.x, b1.y};
            float av[8] = {a0.x, a0.y, a0.z, a0.w, a1.x, a1.y, a1.z, a1.w};
#pragma unroll
            for (int i = 0; i < 8; i++) {
                u64 ai = pack2(av[i], av[i]);
#pragma unroll
                for (int j = 0; j < 4; j++) ffma2(acc[i][j], ai, bb[j]);
            }
        }

        if (c + 1 < nch) {
            const int nbuf = buf ^ 1;
            float av0[4] = {ra0.x, ra0.y, ra0.z, ra0.w};
            float av1[4] = {ra1.x, ra1.y, ra1.z, ra1.w};
            float bv0[4] = {rb0.x, rb0.y, rb0.z, rb0.w};
            float bv1[4] = {rb1.x, rb1.y, rb1.z, rb1.w};
#pragma unroll
            for (int j = 0; j < 4; j++) {
                As[nbuf][lc + j][lr]      = av0[j];
                As[nbuf][lc + j][lr + 64] = av1[j];
                Bs[nbuf][lc + j][bo0]     = bv0[j];
                Bs[nbuf][lc + j][bo1]     = bv1[j];
            }
            __syncthreads();
        }
    }

    const int mBase = mb + ty * 8;
    const int nBase = nb + tx * 8;
#pragma unroll
    for (int i = 0; i < 8; i++) {
        float o[8];
#pragma unroll
        for (int j = 0; j < 4; j++) unpack2(acc[i][j], o[j * 2], o[j * 2 + 1]);
        float* cp = C + (size_t)(mBase + i) * N + nBase;
        *(float4*)(cp)     = make_float4(o[0], o[1], o[2], o[3]);
        *(float4*)(cp + 4) = make_float4(o[4], o[5], o[6], o[7]);
    }
}

// Fused QKV projection: grid.x spans 32 col-blocks (16 Q | 8 K | 8 V)
__global__ __launch_bounds__(256) void qkv_gemm(
        const float* __restrict__ x,
        const float* __restrict__ Wq, const float* __restrict__ Wk,
        const float* __restrict__ Wv,
        float* __restrict__ Cq, float* __restrict__ Ck, float* __restrict__ Cv)
{
    __shared__ float As[2][16][GPAD];
    __shared__ float Bs[2][16][GPAD];

    const int mb = blockIdx.y * 128;
    const int xb = blockIdx.x;
    const float* W; float* C; int nb, N;
    if (xb < 16)      { W = Wq; C = Cq; nb = xb * 128;        N = NH  * HD; }
    else if (xb < 24) { W = Wk; C = Ck; nb = (xb - 16) * 128; N = NKV * HD; }
    else              { W = Wv; C = Cv; nb = (xb - 24) * 128; N = NKV * HD; }

    gemm_core(x + (size_t)mb * HID, W + (size_t)nb * HID, C, N, HID, mb, nb,
              As, Bs);
}

__global__ __launch_bounds__(256) void sgemm_f32x2(
        const float* __restrict__ A, const float* __restrict__ Bw,
        float* __restrict__ C, int N, int K)
{
    __shared__ float As[2][16][GPAD];
    __shared__ float Bs[2][16][GPAD];
    const int mb = blockIdx.y * 128;
    const int nb = blockIdx.x * 128;
    gemm_core(A + (size_t)mb * K, Bw + (size_t)nb * K, C, N, K, mb, nb, As, Bs);
}

// ---------------- fused RMSNorm + RoPE (generic head count) ----------------
__global__ __launch_bounds__(128) void rmsnorm_rope_kernel(
        float* __restrict__ base, int heads,
        const float* __restrict__ cosb, const float* __restrict__ sinb,
        const float* __restrict__ w)
{
    const int idx  = blockIdx.x;
    const int head = idx % heads;
    const int bl   = idx / heads;
    const int d    = threadIdx.x;

    float* vec = base + ((size_t)bl * heads + head) * HD;

    float val = vec[d];
    float ss  = val * val;
#pragma unroll
    for (int o = 16; o > 0; o >>= 1) ss += __shfl_xor_sync(0xffffffffu, ss, o);
    __shared__ float wsum[4];
    if ((d & 31) == 0) wsum[d >> 5] = ss;
    __syncthreads();
    float tot = wsum[0] + wsum[1] + wsum[2] + wsum[3];
    float r   = rsqrtf(tot * (1.0f/HD) + 1e-6f);
    float nv  = val * r * w[d];

    __shared__ float sv[HD];
    sv[d] = nv;
    __syncthreads();

    const float* cp = cosb + (size_t)bl * HD;
    const float* sp = sinb + (size_t)bl * HD;
    float outv;
    if (d < 64) outv = nv * cp[d]    - sv[d+64] * sp[d];
    else        outv = nv * cp[d-64] + sv[d-64] * sp[d-64];
    vec[d] = outv;
}

// ---------------- flash attention: R11 thread layout, 64-query CTA ---------
// CTA = (b, kvh, q-block of 64), 256 threads. hg = tid>>7 -> head 2*kvh+hg.
// Head-group (128 thr): sub8 = t&7 owns dims sub8*16..+16; qs = t>>3 (0..15)
// owns queries q0+qs+{0,16,32,48} (4 q/thread — R11's measured optimum of
// 32B smem lane-traffic per query*kk). vs R11: same warps/SM, but tile
// loads + syncs per unit work HALVED (64 queries share each K/V tile).
// Conflict-free skewed smem (segment s at s*20). Fixed-offset softmax.
#define AROW 160
__global__ __launch_bounds__(256, 1) void attn_kernel(
        const float* __restrict__ Q, const float* __restrict__ Kb,
        const float* __restrict__ Vb, float* __restrict__ O)
{
    __shared__ float Ks[32][AROW];
    __shared__ float Vs[32][AROW];

    const int tid = threadIdx.x;
    const int hg  = tid >> 7;          // head group 0/1
    const int t2  = tid & 127;
    const int sub8 = t2 & 7;           // 16-dim segment
    const int qs  = t2 >> 3;           // 0..15
    const int b   = blockIdx.z;
    const int kvh = blockIdx.y;
    const int h   = kvh * 2 + hg;
    const int q0  = blockIdx.x * 64;

    int qrow[4];
#pragma unroll
    for (int e = 0; e < 4; e++) qrow[e] = q0 + qs + e * 16;

    const float scale = 0.08838834764831844f;   // 1/sqrt(128)
    u64 q2[4][8];
#pragma unroll
    for (int e = 0; e < 4; e++) {
        const float* qpp = Q + (((size_t)b*LSEQ + qrow[e])*NH + h)*HD + sub8*16;
#pragma unroll
        for (int j = 0; j < 8; j++) {
            float2 v = *(const float2*)(qpp + j*2);
            q2[e][j] = pack2(v.x * scale, v.y * scale);
        }
    }

    float l[4] = {0.f, 0.f, 0.f, 0.f};
    u64 acc[4][8];
#pragma unroll
    for (int e = 0; e < 4; e++)
#pragma unroll
        for (int j = 0; j < 8; j++) acc[e][j] = 0ull;

    const bool img = (q0 < NIMG);
    const int nk = img ? (LSEQ/32) : (q0/32 + 2);   // 64-q block: 2 diag tiles
    const int nfull = img ? nk : (q0/32);
    const int segoff = sub8 * 20;

    for (int t = 0; t < nk; t++) {
        const int k0 = t * 32;
        const size_t kbase = (((size_t)b*LSEQ + k0)*NKV + kvh)*HD;
#pragma unroll
        for (int i = 0; i < 4; i++) {
            int idx = tid + i*256;          // 0..1023
            int row = idx >> 5;
            int c   = (idx & 31) << 2;
            int so  = row * AROW + (c >> 4) * 20 + (c & 15);
            size_t g = kbase + (size_t)row*NKV*HD + c;
            *(float4*)&Ks[0][so] = *(const float4*)(Kb + g);
            *(float4*)&Vs[0][so] = *(const float4*)(Vb + g);
        }
        __syncthreads();

        const bool need_mask = (t >= nfull);

#pragma unroll
        for (int kk = 0; kk < 32; kk++) {
            const ulonglong2* kr = (const ulonglong2*)&Ks[kk][segoff];
            ulonglong2 k01 = kr[0], k23 = kr[1], k45 = kr[2], k67 = kr[3];
            u64 kv[8] = {k01.x, k01.y, k23.x, k23.y, k45.x, k45.y, k67.x, k67.y};

            float p[4];
#pragma unroll
            for (int e = 0; e < 4; e++) {
                u64 p2 = 0ull;
#pragma unroll
                for (int j = 0; j < 8; j++) ffma2(p2, q2[e][j], kv[j]);
                float x, y;
                unpack2(p2, x, y);
                p[e] = x + y;
            }
#pragma unroll
            for (int e = 0; e < 4; e++) {
                p[e] += __shfl_xor_sync(0xffffffffu, p[e], 1);
                p[e] += __shfl_xor_sync(0xffffffffu, p[e], 2);
                p[e] += __shfl_xor_sync(0xffffffffu, p[e], 4);
            }

            float ee[4];
#pragma unroll
            for (int e = 0; e < 4; e++) {
                float ev = __expf(p[e] - 16.f);
                if (need_mask && (k0 + kk > qrow[e])) ev = 0.f;
                ee[e] = ev;
                l[e] += ev;
            }

            const ulonglong2* vr = (const ulonglong2*)&Vs[kk][segoff];
            ulonglong2 v01 = vr[0], v23 = vr[1], v45 = vr[2], v67 = vr[3];
            u64 vv[8] = {v01.x, v01.y, v23.x, v23.y, v45.x, v45.y, v67.x, v67.y};
#pragma unroll
            for (int e = 0; e < 4; e++) {
                u64 pe = pack2(ee[e], ee[e]);
#pragma unroll
                for (int j = 0; j < 8; j++) ffma2(acc[e][j], pe, vv[j]);
            }
        }
        __syncthreads();
    }

#pragma unroll
    for (int e = 0; e < 4; e++) {
        const float inv = 1.f / l[e];
        float* op = O + (((size_t)b*LSEQ + qrow[e])*NH + h)*HD + sub8*16;
#pragma unroll
        for (int j = 0; j < 4; j++) {
            float x, y, zx, zy;
            unpack2(acc[e][j*2],   x,  y);
            unpack2(acc[e][j*2+1], zx, zy);
            *(float4*)(op + j*4) = make_float4(x*inv, y*inv, zx*inv, zy*inv);
        }
    }
}

// ---------------- launch ----------------------------------------------------
// 5 launches; #4 (profiled) = attention.
extern "C" void kernel_launch(void* const* d_in, const int* in_sizes, int n_in,
                              void* d_out, int out_size)
{
    const float* x    = (const float*)d_in[0];
    const float* cosb = (const float*)d_in[1];
    const float* sinb = (const float*)d_in[2];
    // d_in[3] = attention_mask (recomputed analytically, unused)
    const float* Wq   = (const float*)d_in[4];
    const float* Wk   = (const float*)d_in[5];
    const float* Wv   = (const float*)d_in[6];
    const float* Wo   = (const float*)d_in[7];
    const float* qw   = (const float*)d_in[8];
    const float* kw   = (const float*)d_in[9];
    float* out = (float*)d_out;

    float *gq, *gk, *gv, *gao;
    cudaGetSymbolAddress((void**)&gq,  g_q);
    cudaGetSymbolAddress((void**)&gk,  g_k);
    cudaGetSymbolAddress((void**)&gv,  g_v);
    cudaGetSymbolAddress((void**)&gao, g_ao);

    // 1: fused QKV projection (R11 config)
    qkv_gemm<<<dim3(32, MROWS/128), 256>>>(x, Wq, Wk, Wv, gq, gk, gv);

    // 2,3: RMSNorm + RoPE (R11 config)
    rmsnorm_rope_kernel<<<BATCH*LSEQ*NH,  128>>>(gq, NH,  cosb, sinb, qw);
    rmsnorm_rope_kernel<<<BATCH*LSEQ*NKV, 128>>>(gk, NKV, cosb, sinb, kw);

    // 4: attention (profiled slot) — 64-query CTAs, R11 thread layout
    attn_kernel<<<dim3(LSEQ/64, NKV, BATCH), 256>>>(gq, gk, gv, gao);

    // 5: output projection (R11 config)
    sgemm_f32x2<<<dim3(HID/128, MROWS/128), 256>>>(gao, Wo, out, HID, NH*HD);
}